// round 3
// baseline (speedup 1.0000x reference)
#include <cuda_runtime.h>

// ---------------------------------------------------------------------------
// ChannelAttentionModule (DANet): out = beta * softmax(rowmax(G)-G) @ feat + x
// where G = feat @ feat^T, feat = x.reshape(B, C, H*W).
// B=32, C=512, N=H*W=1024, fp32.
//
// Stage 1: Gram (symmetric, upper-tri tile pairs only, mirrored on write)
// Stage 2: row-wise softmin normalize in place: w = exp(min-s)/sum
// Stage 3: out = beta * (W @ feat) + x
// All fp32 math via packed fma.rn.f32x2 (SASS FFMA2, 2x fp32 throughput).
// ---------------------------------------------------------------------------

#define BDIM 32
#define CDIM 512
#define NDIM 1024

#define BM 128
#define BK 16
#define PAD 132   // smem row stride (floats): 16B-aligned, breaks store conflicts

// 32 MB scratch for attention scores/weights (static device global: allowed).
__device__ float g_scores[(size_t)BDIM * CDIM * CDIM];

typedef unsigned long long u64;

__device__ __forceinline__ u64 pack_dup(float a) {
    u64 r;
    asm("mov.b64 %0, {%1, %1};" : "=l"(r) : "f"(a));
    return r;
}
__device__ __forceinline__ void unpack2(u64 v, float& lo, float& hi) {
    asm("mov.b64 {%0, %1}, %2;" : "=f"(lo), "=f"(hi) : "l"(v));
}
__device__ __forceinline__ u64 fma2(u64 a, u64 b, u64 c) {
    u64 d;
    asm("fma.rn.f32x2 %0, %1, %2, %3;" : "=l"(d) : "l"(a), "l"(b), "l"(c));
    return d;
}

// ---------------------------------------------------------------------------
// Stage 1: Gram matrix S[b] = feat[b] @ feat[b]^T   (C x C, K = NDIM)
// Exploits symmetry: grid.x enumerates the 10 upper-triangular 128x128 tile
// pairs of the 4x4 tile grid; off-diagonal results are mirrored.
// ---------------------------------------------------------------------------
__global__ __launch_bounds__(256, 2)
void gram_kernel(const float* __restrict__ x) {
    const int b = blockIdx.y;
    int p = blockIdx.x;
    int ti = 0;
    while (p >= 4 - ti) { p -= 4 - ti; ti++; }
    const int tj = ti + p;   // ti <= tj

    const float* fa = x + (size_t)b * CDIM * NDIM + (size_t)ti * BM * NDIM;
    const float* fb = x + (size_t)b * CDIM * NDIM + (size_t)tj * BM * NDIM;

    __shared__ __align__(16) float As[BK][PAD];
    __shared__ __align__(16) float Bs[BK][PAD];

    const int t  = threadIdx.x;
    const int tx = t & 15, ty = t >> 4;
    const int m0 = ty * 8, n0 = tx * 8;

    u64 acc[8][4];
#pragma unroll
    for (int i = 0; i < 8; i++)
#pragma unroll
        for (int j = 0; j < 4; j++) acc[i][j] = 0ull;

    for (int k0 = 0; k0 < NDIM; k0 += BK) {
#pragma unroll
        for (int i = 0; i < 2; i++) {
            const int f   = t + i * 256;       // 0..511
            const int row = f >> 2;            // 0..127
            const int c4  = (f & 3) << 2;      // 0,4,8,12
            float4 va = *(const float4*)(fa + (size_t)row * NDIM + k0 + c4);
            As[c4 + 0][row] = va.x; As[c4 + 1][row] = va.y;
            As[c4 + 2][row] = va.z; As[c4 + 3][row] = va.w;
            float4 vb = *(const float4*)(fb + (size_t)row * NDIM + k0 + c4);
            Bs[c4 + 0][row] = vb.x; Bs[c4 + 1][row] = vb.y;
            Bs[c4 + 2][row] = vb.z; Bs[c4 + 3][row] = vb.w;
        }
        __syncthreads();
#pragma unroll
        for (int kk = 0; kk < BK; kk++) {
            float4 a0 = *(const float4*)&As[kk][m0];
            float4 a1 = *(const float4*)&As[kk][m0 + 4];
            ulonglong2 bq0 = *(const ulonglong2*)&Bs[kk][n0];
            ulonglong2 bq1 = *(const ulonglong2*)&Bs[kk][n0 + 4];
            const u64 bb0 = bq0.x, bb1 = bq0.y, bb2 = bq1.x, bb3 = bq1.y;
            float ar[8] = {a0.x, a0.y, a0.z, a0.w, a1.x, a1.y, a1.z, a1.w};
#pragma unroll
            for (int m = 0; m < 8; m++) {
                const u64 a2 = pack_dup(ar[m]);
                acc[m][0] = fma2(a2, bb0, acc[m][0]);
                acc[m][1] = fma2(a2, bb1, acc[m][1]);
                acc[m][2] = fma2(a2, bb2, acc[m][2]);
                acc[m][3] = fma2(a2, bb3, acc[m][3]);
            }
        }
        __syncthreads();
    }

    float* Cb = g_scores + (size_t)b * CDIM * CDIM;
    const int r0 = ti * BM + m0;
    const int c0 = tj * BM + n0;
#pragma unroll
    for (int m = 0; m < 8; m++) {
        float v[8];
        unpack2(acc[m][0], v[0], v[1]);
        unpack2(acc[m][1], v[2], v[3]);
        unpack2(acc[m][2], v[4], v[5]);
        unpack2(acc[m][3], v[6], v[7]);
        float4* dst = (float4*)(Cb + (size_t)(r0 + m) * CDIM + c0);
        dst[0] = make_float4(v[0], v[1], v[2], v[3]);
        dst[1] = make_float4(v[4], v[5], v[6], v[7]);
        if (ti != tj) {
#pragma unroll
            for (int n = 0; n < 8; n++)
                Cb[(size_t)(c0 + n) * CDIM + (r0 + m)] = v[n];
        }
    }
}

// ---------------------------------------------------------------------------
// Stage 2: in-place softmin normalize each row of S.
// softmax(rowmax - S) == exp(rowmin - S) / sum(exp(rowmin - S)).
// One 128-thread block per (batch, row); 4 floats / thread.
// ---------------------------------------------------------------------------
__global__ void softmin_kernel() {
    float* row = g_scores + ((size_t)blockIdx.y * CDIM + blockIdx.x) * CDIM;
    const int t = threadIdx.x;           // 0..127
    const int warp = t >> 5, lane = t & 31;

    float4 v = ((float4*)row)[t];
    float mn = fminf(fminf(v.x, v.y), fminf(v.z, v.w));
#pragma unroll
    for (int o = 16; o > 0; o >>= 1)
        mn = fminf(mn, __shfl_xor_sync(0xffffffffu, mn, o));

    __shared__ float rmin[4], rsum[4];
    if (lane == 0) rmin[warp] = mn;
    __syncthreads();
    mn = fminf(fminf(rmin[0], rmin[1]), fminf(rmin[2], rmin[3]));

    float4 e;
    e.x = __expf(mn - v.x); e.y = __expf(mn - v.y);
    e.z = __expf(mn - v.z); e.w = __expf(mn - v.w);
    float s = e.x + e.y + e.z + e.w;
#pragma unroll
    for (int o = 16; o > 0; o >>= 1)
        s += __shfl_xor_sync(0xffffffffu, s, o);
    if (lane == 0) rsum[warp] = s;
    __syncthreads();
    s = rsum[0] + rsum[1] + rsum[2] + rsum[3];

    const float inv = __frcp_rn(s);
    e.x *= inv; e.y *= inv; e.z *= inv; e.w *= inv;
    ((float4*)row)[t] = e;
}

// ---------------------------------------------------------------------------
// Stage 3: out = beta * (W @ feat) + x     (M=C=512, N=NDIM=1024, K=C=512)
// ---------------------------------------------------------------------------
__global__ __launch_bounds__(256, 2)
void av_kernel(const float* __restrict__ x, const float* __restrict__ beta,
               float* __restrict__ out) {
    const int b    = blockIdx.z;
    const int nblk = blockIdx.x;   // 0..7  (N tiles)
    const int mblk = blockIdx.y;   // 0..3  (M tiles)

    const float* W = g_scores + (size_t)b * CDIM * CDIM + (size_t)mblk * BM * CDIM;
    const float* F = x + (size_t)b * CDIM * NDIM + (size_t)nblk * BM;

    __shared__ __align__(16) float As[BK][PAD];
    __shared__ __align__(16) float Bs[BK][PAD];

    const int t  = threadIdx.x;
    const int tx = t & 15, ty = t >> 4;
    const int m0 = ty * 8, n0 = tx * 8;

    u64 acc[8][4];
#pragma unroll
    for (int i = 0; i < 8; i++)
#pragma unroll
        for (int j = 0; j < 4; j++) acc[i][j] = 0ull;

    for (int k0 = 0; k0 < CDIM; k0 += BK) {
#pragma unroll
        for (int i = 0; i < 2; i++) {
            const int f = t + i * 256;
            {   // A tile [128 rows x 16 k], transpose into As[k][m]
                const int row = f >> 2;
                const int c4  = (f & 3) << 2;
                float4 va = *(const float4*)(W + (size_t)row * CDIM + k0 + c4);
                As[c4 + 0][row] = va.x; As[c4 + 1][row] = va.y;
                As[c4 + 2][row] = va.z; As[c4 + 3][row] = va.w;
            }
            {   // B tile [16 k x 128 n], direct copy
                const int kk = f >> 5;           // 0..15
                const int nc = (f & 31) << 2;    // 0..124
                float4 vb = *(const float4*)(F + (size_t)(k0 + kk) * NDIM + nc);
                *(float4*)&Bs[kk][nc] = vb;
            }
        }
        __syncthreads();
#pragma unroll
        for (int kk = 0; kk < BK; kk++) {
            float4 a0 = *(const float4*)&As[kk][m0];
            float4 a1 = *(const float4*)&As[kk][m0 + 4];
            ulonglong2 bq0 = *(const ulonglong2*)&Bs[kk][n0];
            ulonglong2 bq1 = *(const ulonglong2*)&Bs[kk][n0 + 4];
            const u64 bb0 = bq0.x, bb1 = bq0.y, bb2 = bq1.x, bb3 = bq1.y;
            float ar[8] = {a0.x, a0.y, a0.z, a0.w, a1.x, a1.y, a1.z, a1.w};
#pragma unroll
            for (int m = 0; m < 8; m++) {
                const u64 a2 = pack_dup(ar[m]);
                acc[m][0] = fma2(a2, bb0, acc[m][0]);
                acc[m][1] = fma2(a2, bb1, acc[m][1]);
                acc[m][2] = fma2(a2, bb2, acc[m][2]);
                acc[m][3] = fma2(a2, bb3, acc[m][3]);
            }
        }
        __syncthreads();
    }

    const float beta0 = beta[0];
    const size_t obase = (size_t)b * CDIM * NDIM + (size_t)mblk * BM * NDIM
                       + (size_t)nblk * BM;
#pragma unroll
    for (int m = 0; m < 8; m++) {
        float v[8];
        unpack2(acc[m][0], v[0], v[1]);
        unpack2(acc[m][1], v[2], v[3]);
        unpack2(acc[m][2], v[4], v[5]);
        unpack2(acc[m][3], v[6], v[7]);
        const size_t off = obase + (size_t)(m0 + m) * NDIM + n0;
        const float4* xr = (const float4*)(x + off);
        float4 x0 = xr[0], x1 = xr[1];
        float4* o4 = (float4*)(out + off);
        o4[0] = make_float4(fmaf(beta0, v[0], x0.x), fmaf(beta0, v[1], x0.y),
                            fmaf(beta0, v[2], x0.z), fmaf(beta0, v[3], x0.w));
        o4[1] = make_float4(fmaf(beta0, v[4], x1.x), fmaf(beta0, v[5], x1.y),
                            fmaf(beta0, v[6], x1.z), fmaf(beta0, v[7], x1.w));
    }
}

// ---------------------------------------------------------------------------
extern "C" void kernel_launch(void* const* d_in, const int* in_sizes, int n_in,
                              void* d_out, int out_size) {
    (void)n_in; (void)out_size;
    const float* x    = (const float*)d_in[0];
    const float* beta = (const float*)d_in[1];
    if (in_sizes[0] == 1) {  // defensive: metadata order beta,x
        const float* tmp = x; x = beta; beta = tmp;
    }
    float* out = (float*)d_out;

    gram_kernel<<<dim3(10, BDIM), 256>>>(x);
    softmin_kernel<<<dim3(CDIM, BDIM), 128>>>();
    av_kernel<<<dim3(NDIM / BM, CDIM / BM, BDIM), 256>>>(x, beta, out);
}